// round 8
// baseline (speedup 1.0000x reference)
#include <cuda_runtime.h>

// Problem constants (from reference)
#define B        4096
#define N_ELEM   2048
#define N_NODES  1024
#define E2       4096
#define NGROUPS  B                     // G=1: one batch per group
#define NBLK     304                   // 2 CTAs/SM x 152 SMs, persistent
#define THREADS  512
#define NODES_PT (N_NODES / THREADS)   // 2 nodes per thread

// __device__ scratch (16B-aligned for cp.async.bulk sources).
__device__ __align__(16) int    g_elem[E2];
__device__ __align__(16) float2 g_vec[E2];
__device__ __align__(16) int    g_off[N_NODES + 4];
__device__ float g_part[NBLK];
__device__ int   g_ctr = 0;

// Dynamic smem layout (bytes), total 96KB -> 2 CTAs/SM:
#define OFF_ELEM   0                    // int[E2]          16K
#define OFF_VEC    (16 * 1024)          // float2[E2]       32K
#define OFF_OFF    (48 * 1024)          // int[N_NODES+4]   ~4K
#define OFF_AXIAL  (56 * 1024)          // float[N_ELEM]     8K
#define OFF_BUF0   (64 * 1024)          // 16K: [EA row | e row]
#define OFF_BUF1   (80 * 1024)          // 16K
#define SMEM_BYTES (96 * 1024)

#define CSR_BYTES   (16384 + 32768 + 4112)
#define GRP_BYTES   (2 * 8192)          // EA row + e row

__device__ __forceinline__ unsigned smem_u32(const void* p) {
    return (unsigned)__cvta_generic_to_shared(p);
}
__device__ __forceinline__ void mbar_init(unsigned mbar, unsigned count) {
    asm volatile("mbarrier.init.shared.b64 [%0], %1;" :: "r"(mbar), "r"(count) : "memory");
}
__device__ __forceinline__ void mbar_expect_tx(unsigned mbar, unsigned bytes) {
    asm volatile("mbarrier.arrive.expect_tx.shared.b64 _, [%0], %1;"
                 :: "r"(mbar), "r"(bytes) : "memory");
}
__device__ __forceinline__ void mbar_wait(unsigned mbar, unsigned parity) {
    asm volatile(
        "{\n\t.reg .pred P;\n\t"
        "W%=:\n\t"
        "mbarrier.try_wait.parity.acquire.cta.shared::cta.b64 P, [%0], %1, 0x989680;\n\t"
        "@!P bra W%=;\n\t}"
        :: "r"(mbar), "r"(parity) : "memory");
}
__device__ __forceinline__ void bulk_g2s(unsigned dst_smem, const void* src,
                                         unsigned bytes, unsigned mbar) {
    asm volatile(
        "cp.async.bulk.shared::cta.global.mbarrier::complete_tx::bytes [%0], [%1], %2, [%3];"
        :: "r"(dst_smem), "l"(src), "r"(bytes), "r"(mbar) : "memory");
}

// ---------------------------------------------------------------------------
// Setup: deterministic CSR (edges grouped by node, sorted by original edge
// index within each node). One block, 1024 threads.
// ---------------------------------------------------------------------------
__global__ __launch_bounds__(N_NODES)
void nel_setup_kernel(const int* __restrict__ node_ids,
                      const int* __restrict__ elem_ids,
                      const float* __restrict__ vecs) {
    __shared__ int s_beg[N_NODES];
    __shared__ int s_cur[N_NODES];
    __shared__ int s_idx[E2];
    __shared__ int s_wsum[32];
    const int tid  = threadIdx.x;
    const int lane = tid & 31;
    const int wrp  = tid >> 5;

    // 1. histogram
    s_beg[tid] = 0;
    __syncthreads();
    #pragma unroll
    for (int i = tid; i < E2; i += N_NODES)
        atomicAdd(&s_beg[node_ids[i]], 1);
    __syncthreads();

    // 2. exclusive scan via warp shuffles
    const int cnt = s_beg[tid];
    int v = cnt;
    #pragma unroll
    for (int o = 1; o < 32; o <<= 1) {
        int t = __shfl_up_sync(0xffffffffu, v, o);
        if (lane >= o) v += t;
    }
    if (lane == 31) s_wsum[wrp] = v;
    __syncthreads();
    if (wrp == 0) {
        int w = s_wsum[lane];
        #pragma unroll
        for (int o = 1; o < 32; o <<= 1) {
            int t = __shfl_up_sync(0xffffffffu, w, o);
            if (lane >= o) w += t;
        }
        s_wsum[lane] = w - s_wsum[lane];
    }
    __syncthreads();
    const int excl = v - cnt + s_wsum[wrp];
    s_beg[tid] = excl;
    s_cur[tid] = excl;
    __syncthreads();

    // 3. scatter edge indices into bins
    #pragma unroll
    for (int i = tid; i < E2; i += N_NODES) {
        int pos = atomicAdd(&s_cur[node_ids[i]], 1);
        s_idx[pos] = i;
    }
    __syncthreads();

    // 4. per-bin insertion sort -> deterministic edge order
    {
        const int beg = s_beg[tid], end = s_cur[tid];
        for (int a = beg + 1; a < end; a++) {
            int key = s_idx[a];
            int p = a - 1;
            while (p >= beg && s_idx[p] > key) { s_idx[p + 1] = s_idx[p]; p--; }
            s_idx[p + 1] = key;
        }
    }
    __syncthreads();

    // 5. write split CSR arrays
    g_off[tid] = s_beg[tid];
    if (tid == 0) {
        g_off[N_NODES] = E2; g_off[N_NODES + 1] = E2;
        g_off[N_NODES + 2] = E2; g_off[N_NODES + 3] = E2;
    }
    #pragma unroll
    for (int i = tid; i < E2; i += N_NODES) {
        int idx = s_idx[i];
        g_elem[i] = elem_ids[idx];
        g_vec[i]  = make_float2(vecs[2 * idx], vecs[2 * idx + 1]);
    }
}

// ---------------------------------------------------------------------------
// Main: 304 persistent blocks, 2 CTAs/SM (512 thr, 96KB smem each) so one
// CTA's compute covers the other's TMA/barrier tails. G=1 batch per group,
// EA/e via TMA double-buffer; q/r streamed via coalesced LDG.
// ---------------------------------------------------------------------------
__global__ __launch_bounds__(THREADS, 2)
void nel_main_kernel(const float* __restrict__ EA,
                     const float* __restrict__ e,
                     const float* __restrict__ q,
                     const float* __restrict__ r,
                     float* __restrict__ out) {
    extern __shared__ unsigned char dyn[];
    int*    s_elem  = (int*)   (dyn + OFF_ELEM);
    float2* s_vec   = (float2*)(dyn + OFF_VEC);
    int*    s_off   = (int*)   (dyn + OFF_OFF);
    float*  s_axial = (float*) (dyn + OFF_AXIAL);
    float*  s_buf0  = (float*) (dyn + OFF_BUF0);
    float*  s_buf1  = (float*) (dyn + OFF_BUF1);
    __shared__ __align__(8) unsigned long long s_mbar[2];
    __shared__ float s_warp[THREADS / 32];
    __shared__ int   s_islast;

    const int tid = threadIdx.x;
    const int g0  = blockIdx.x;
    const int cnt = (NGROUPS - g0 + NBLK - 1) / NBLK;
    const unsigned mb0 = smem_u32(&s_mbar[0]);
    const unsigned mb1 = smem_u32(&s_mbar[1]);

    if (tid == 0) { mbar_init(mb0, 1); mbar_init(mb1, 1); }
    __syncthreads();

    // --- prologue: CSR + group 0 on mb0, group 1 on mb1 ---
    if (tid == 0) {
        {
            int grp = g0;
            mbar_expect_tx(mb0, CSR_BYTES + GRP_BYTES);
            bulk_g2s(smem_u32(s_elem), g_elem, 16384, mb0);
            bulk_g2s(smem_u32(s_vec),  g_vec,  32768, mb0);
            bulk_g2s(smem_u32(s_off),  g_off,  4112,  mb0);
            bulk_g2s(smem_u32(s_buf0),        EA + (size_t)grp * N_ELEM, 8192, mb0);
            bulk_g2s(smem_u32(s_buf0 + 2048), e  + (size_t)grp * N_ELEM, 8192, mb0);
        }
        if (cnt > 1) {
            int grp = g0 + NBLK;
            mbar_expect_tx(mb1, GRP_BYTES);
            bulk_g2s(smem_u32(s_buf1),        EA + (size_t)grp * N_ELEM, 8192, mb1);
            bulk_g2s(smem_u32(s_buf1 + 2048), e  + (size_t)grp * N_ELEM, 8192, mb1);
        }
    }

    float acc = 0.f;
    unsigned ph0 = 0, ph1 = 0;
    int beg0 = 0, end0 = 0, beg1 = 0, end1 = 0;
    const int n0 = tid, n1 = tid + THREADS;

    for (int k = 0; k < cnt; k++) {
        const int grp  = g0 + k * NBLK;
        const int bsel = k & 1;
        float* buf = bsel ? s_buf1 : s_buf0;
        const unsigned mb = bsel ? mb1 : mb0;

        if (bsel) { mbar_wait(mb, ph1); ph1 ^= 1; }
        else      { mbar_wait(mb, ph0); ph0 ^= 1; }

        if (k == 0) {                 // CSR just arrived: cache node spans
            beg0 = s_off[n0]; end0 = s_off[n0 + 1];
            beg1 = s_off[n1]; end1 = s_off[n1 + 1];
        }

        // --- early-issue q/r streaming loads (coalesced, hide under gather) ---
        const float2* q2 = (const float2*)(q + (size_t)grp * N_NODES * 2);
        const float2* r2 = (const float2*)(r + (size_t)grp * N_NODES * 2);
        const float2 qq0 = __ldg(&q2[n0]);
        const float2 rr0 = __ldg(&r2[n0]);
        const float2 qq1 = __ldg(&q2[n1]);
        const float2 rr1 = __ldg(&r2[n1]);

        // --- build axial = EA * e ---
        #pragma unroll
        for (int i = tid; i < N_ELEM; i += THREADS)
            s_axial[i] = buf[i] * buf[2048 + i];
        __syncthreads();

        // --- prefetch group k+2 into this buffer's successor slot ---
        if (tid == 0 && k + 2 < cnt) {
            int ng = g0 + (k + 2) * NBLK;
            float* nbuf = bsel ? s_buf1 : s_buf0;   // same buffer reused
            mbar_expect_tx(mb, GRP_BYTES);
            // NOTE: refill is deferred until after gather (see below) — here we
            // only declare the expected bytes; the copies are issued post-bar.
            bulk_g2s(smem_u32(nbuf),        EA + (size_t)ng * N_ELEM, 8192, mb);
            bulk_g2s(smem_u32(nbuf + 2048), e  + (size_t)ng * N_ELEM, 8192, mb);
        }

        // --- gather + loss for this thread's 2 nodes ---
        float ax0 = 0.f, ay0 = 0.f;
        for (int p = beg0; p < end0; p++) {
            float2 v = s_vec[p];
            float  a = s_axial[s_elem[p]];
            ax0 += a * v.x;  ay0 += a * v.y;
        }
        float ax1 = 0.f, ay1 = 0.f;
        for (int p = beg1; p < end1; p++) {
            float2 v = s_vec[p];
            float  a = s_axial[s_elem[p]];
            ax1 += a * v.x;  ay1 += a * v.y;
        }
        float dx0 = ax0 - qq0.x - rr0.x, dy0 = ay0 - qq0.y - rr0.y;
        float dx1 = ax1 - qq1.x - rr1.x, dy1 = ay1 - qq1.y - rr1.y;
        acc += dx0 * dx0 + dy0 * dy0 + dx1 * dx1 + dy1 * dy1;

        __syncthreads();   // axial/buf fully consumed before next build
    }

    // --- block reduce ---
    #pragma unroll
    for (int o = 16; o > 0; o >>= 1)
        acc += __shfl_down_sync(0xffffffffu, acc, o);
    if ((tid & 31) == 0) s_warp[tid >> 5] = acc;
    __syncthreads();
    if (tid == 0) {
        float total = 0.f;
        #pragma unroll
        for (int w = 0; w < THREADS / 32; w++) total += s_warp[w];
        g_part[blockIdx.x] = total;
    }

    // --- last-block finalize (fixed-order double sum -> deterministic) ---
    __threadfence();
    if (tid == 0) {
        int old = atomicAdd(&g_ctr, 1);
        s_islast = (old == (int)gridDim.x - 1) ? 1 : 0;
    }
    __syncthreads();
    if (s_islast) {
        __threadfence();
        __shared__ double s_d[THREADS];
        double d = 0.0;
        #pragma unroll
        for (int i = tid; i < NBLK; i += THREADS) d += (double)g_part[i];
        s_d[tid] = d;
        __syncthreads();
        #pragma unroll
        for (int s = THREADS / 2; s > 0; s >>= 1) {
            if (tid < s) s_d[tid] += s_d[tid + s];
            __syncthreads();
        }
        if (tid == 0) {
            out[0] = (float)(s_d[0] / ((double)B * (double)N_NODES * 2.0));
            g_ctr = 0;   // reset for next graph replay
        }
    }
}

extern "C" void kernel_launch(void* const* d_in, const int* in_sizes, int n_in,
                              void* d_out, int out_size) {
    const float* EA       = (const float*)d_in[0];
    const float* e        = (const float*)d_in[1];
    const float* q        = (const float*)d_in[2];
    const float* r        = (const float*)d_in[3];
    const float* vecs     = (const float*)d_in[4];
    const int*   node_ids = (const int*)d_in[5];
    const int*   elem_ids = (const int*)d_in[6];
    float* out = (float*)d_out;

    static int configured = 0;
    if (!configured) {
        cudaFuncSetAttribute(nel_main_kernel,
                             cudaFuncAttributeMaxDynamicSharedMemorySize,
                             SMEM_BYTES);
        configured = 1;
    }

    nel_setup_kernel<<<1, N_NODES>>>(node_ids, elem_ids, vecs);
    nel_main_kernel<<<NBLK, THREADS, SMEM_BYTES>>>(EA, e, q, r, out);
}

// round 10
// speedup vs baseline: 1.3000x; 1.3000x over previous
#include <cuda_runtime.h>

// Problem constants (from reference)
#define B        4096
#define N_ELEM   2048
#define N_NODES  1024
#define E2       4096
#define G        4                     // batches per group
#define NGROUPS  (B / G)               // 1024 groups
#define NBLK     152                   // 1 CTA/SM, persistent
#define THREADS  1024                  // 1 node per thread

// __device__ scratch (16B-aligned for cp.async.bulk sources).
__device__ __align__(16) float4 g_csr[E2];          // {eid_bits, vx, vy, 0}
__device__ __align__(16) int    g_off[N_NODES + 4];
__device__ float g_part[NBLK];
__device__ int   g_ctr = 0;

// Dynamic smem layout (bytes), 224KB total, 1 CTA/SM.
// (Static smem kept <256B; finalize reduction overlays the CSR region.)
#define OFF_CSR    0                    // float4[E2]   64K
#define OFF_AXIAL  (64 * 1024)          // float4[2048] 32K
#define OFF_BUF0   (96 * 1024)          // 64K: [EA g0..g3 | e g0..g3]
#define OFF_BUF1   (160 * 1024)         // 64K
#define SMEM_BYTES (224 * 1024)

#define CSR_BYTES   (E2 * 16)            // 65536
#define GRP_BYTES   (2 * G * N_ELEM * 4) // 65536

__device__ __forceinline__ unsigned smem_u32(const void* p) {
    return (unsigned)__cvta_generic_to_shared(p);
}
__device__ __forceinline__ void mbar_init(unsigned mbar, unsigned count) {
    asm volatile("mbarrier.init.shared.b64 [%0], %1;" :: "r"(mbar), "r"(count) : "memory");
}
__device__ __forceinline__ void mbar_expect_tx(unsigned mbar, unsigned bytes) {
    asm volatile("mbarrier.arrive.expect_tx.shared.b64 _, [%0], %1;"
                 :: "r"(mbar), "r"(bytes) : "memory");
}
__device__ __forceinline__ void mbar_wait(unsigned mbar, unsigned parity) {
    asm volatile(
        "{\n\t.reg .pred P;\n\t"
        "W%=:\n\t"
        "mbarrier.try_wait.parity.acquire.cta.shared::cta.b64 P, [%0], %1, 0x989680;\n\t"
        "@!P bra W%=;\n\t}"
        :: "r"(mbar), "r"(parity) : "memory");
}
__device__ __forceinline__ void bulk_g2s(unsigned dst_smem, const void* src,
                                         unsigned bytes, unsigned mbar) {
    asm volatile(
        "cp.async.bulk.shared::cta.global.mbarrier::complete_tx::bytes [%0], [%1], %2, [%3];"
        :: "r"(dst_smem), "l"(src), "r"(bytes), "r"(mbar) : "memory");
}

// ---------------------------------------------------------------------------
// Setup: deterministic CSR (edges grouped by node, sorted by original edge
// index within each node). One block, 1024 threads.
// ---------------------------------------------------------------------------
__global__ __launch_bounds__(N_NODES)
void nel_setup_kernel(const int* __restrict__ node_ids,
                      const int* __restrict__ elem_ids,
                      const float* __restrict__ vecs) {
    __shared__ int s_beg[N_NODES];
    __shared__ int s_cur[N_NODES];
    __shared__ int s_idx[E2];
    __shared__ int s_wsum[32];
    const int tid  = threadIdx.x;
    const int lane = tid & 31;
    const int wrp  = tid >> 5;

    // 1. histogram
    s_beg[tid] = 0;
    __syncthreads();
    #pragma unroll
    for (int i = tid; i < E2; i += N_NODES)
        atomicAdd(&s_beg[node_ids[i]], 1);
    __syncthreads();

    // 2. exclusive scan via warp shuffles
    const int cnt = s_beg[tid];
    int v = cnt;
    #pragma unroll
    for (int o = 1; o < 32; o <<= 1) {
        int t = __shfl_up_sync(0xffffffffu, v, o);
        if (lane >= o) v += t;
    }
    if (lane == 31) s_wsum[wrp] = v;
    __syncthreads();
    if (wrp == 0) {
        int w = s_wsum[lane];
        #pragma unroll
        for (int o = 1; o < 32; o <<= 1) {
            int t = __shfl_up_sync(0xffffffffu, w, o);
            if (lane >= o) w += t;
        }
        s_wsum[lane] = w - s_wsum[lane];
    }
    __syncthreads();
    const int excl = v - cnt + s_wsum[wrp];
    s_beg[tid] = excl;
    s_cur[tid] = excl;
    __syncthreads();

    // 3. scatter edge indices into bins
    #pragma unroll
    for (int i = tid; i < E2; i += N_NODES) {
        int pos = atomicAdd(&s_cur[node_ids[i]], 1);
        s_idx[pos] = i;
    }
    __syncthreads();

    // 4. per-bin insertion sort -> deterministic edge order
    {
        const int beg = s_beg[tid], end = s_cur[tid];
        for (int a = beg + 1; a < end; a++) {
            int key = s_idx[a];
            int p = a - 1;
            while (p >= beg && s_idx[p] > key) { s_idx[p + 1] = s_idx[p]; p--; }
            s_idx[p + 1] = key;
        }
    }
    __syncthreads();

    // 5. write fused CSR records + offsets
    g_off[tid] = s_beg[tid];
    if (tid == 0) {
        g_off[N_NODES] = E2; g_off[N_NODES + 1] = E2;
        g_off[N_NODES + 2] = E2; g_off[N_NODES + 3] = E2;
    }
    #pragma unroll
    for (int i = tid; i < E2; i += N_NODES) {
        int idx = s_idx[i];
        float4 rec;
        rec.x = __int_as_float(elem_ids[idx]);
        rec.y = vecs[2 * idx];
        rec.z = vecs[2 * idx + 1];
        rec.w = 0.f;
        g_csr[i] = rec;
    }
}

// ---------------------------------------------------------------------------
// Main: 152 persistent blocks (1/SM), 1024 threads, G=4 batches per group.
// Axial as float4 (one LDS.128 serves 4 batches), fused 16B CSR records.
// EA/e via TMA double-buffer; q/r via coalesced LDG issued early.
// ---------------------------------------------------------------------------
__global__ __launch_bounds__(THREADS, 1)
void nel_main_kernel(const float* __restrict__ EA,
                     const float* __restrict__ e,
                     const float* __restrict__ q,
                     const float* __restrict__ r,
                     float* __restrict__ out) {
    extern __shared__ unsigned char dyn[];
    float4* s_csr   = (float4*)(dyn + OFF_CSR);
    float4* s_axial = (float4*)(dyn + OFF_AXIAL);
    float*  s_buf0  = (float*) (dyn + OFF_BUF0);
    float*  s_buf1  = (float*) (dyn + OFF_BUF1);
    __shared__ __align__(8) unsigned long long s_mbar[2];
    __shared__ float s_warp[THREADS / 32];
    __shared__ int   s_islast;

    const int tid = threadIdx.x;
    const int g0  = blockIdx.x;
    const int cnt = (NGROUPS - g0 + NBLK - 1) / NBLK;
    const unsigned mb0 = smem_u32(&s_mbar[0]);
    const unsigned mb1 = smem_u32(&s_mbar[1]);

    if (tid == 0) { mbar_init(mb0, 1); mbar_init(mb1, 1); }
    __syncthreads();

    // node span for this thread (CSR offsets from L2; batch-invariant)
    const int n    = tid;
    const int nbeg = g_off[n];
    const int nend = g_off[n + 1];

    // --- prologue: CSR + group 0 on mb0, group 1 on mb1 ---
    if (tid == 0) {
        {
            int grp = g0;
            mbar_expect_tx(mb0, CSR_BYTES + GRP_BYTES);
            bulk_g2s(smem_u32(s_csr), g_csr, CSR_BYTES, mb0);
            bulk_g2s(smem_u32(s_buf0),
                     EA + (size_t)grp * G * N_ELEM, G * N_ELEM * 4, mb0);
            bulk_g2s(smem_u32(s_buf0 + G * N_ELEM),
                     e  + (size_t)grp * G * N_ELEM, G * N_ELEM * 4, mb0);
        }
        if (cnt > 1) {
            int grp = g0 + NBLK;
            mbar_expect_tx(mb1, GRP_BYTES);
            bulk_g2s(smem_u32(s_buf1),
                     EA + (size_t)grp * G * N_ELEM, G * N_ELEM * 4, mb1);
            bulk_g2s(smem_u32(s_buf1 + G * N_ELEM),
                     e  + (size_t)grp * G * N_ELEM, G * N_ELEM * 4, mb1);
        }
    }

    float acc = 0.f;
    unsigned ph0 = 0, ph1 = 0;

    for (int k = 0; k < cnt; k++) {
        const int grp  = g0 + k * NBLK;
        const int bsel = k & 1;
        float* buf = bsel ? s_buf1 : s_buf0;
        const unsigned mb = bsel ? mb1 : mb0;

        // --- early-issue q/r loads (independent of smem; hide under build) ---
        const float2* q2 = (const float2*)(q + (size_t)grp * G * N_NODES * 2);
        const float2* r2 = (const float2*)(r + (size_t)grp * G * N_NODES * 2);
        float2 qq[G], rr[G];
        #pragma unroll
        for (int g = 0; g < G; g++) {
            qq[g] = __ldg(&q2[g * N_NODES + n]);
            rr[g] = __ldg(&r2[g * N_NODES + n]);
        }

        if (bsel) { mbar_wait(mb, ph1); ph1 ^= 1; }
        else      { mbar_wait(mb, ph0); ph0 ^= 1; }

        // --- build axial4[i] = {EA_g*e_g} for g=0..3 ---
        #pragma unroll
        for (int i = tid; i < N_ELEM; i += THREADS) {
            float4 a;
            a.x = buf[0 * N_ELEM + i] * buf[(G + 0) * N_ELEM + i];
            a.y = buf[1 * N_ELEM + i] * buf[(G + 1) * N_ELEM + i];
            a.z = buf[2 * N_ELEM + i] * buf[(G + 2) * N_ELEM + i];
            a.w = buf[3 * N_ELEM + i] * buf[(G + 3) * N_ELEM + i];
            s_axial[i] = a;
        }
        __syncthreads();   // axial ready; buf free for refill

        // --- refill this buffer with group k+2 (TMA, overlaps gather) ---
        if (tid == 0 && k + 2 < cnt) {
            int ng = g0 + (k + 2) * NBLK;
            mbar_expect_tx(mb, GRP_BYTES);
            bulk_g2s(smem_u32(buf),
                     EA + (size_t)ng * G * N_ELEM, G * N_ELEM * 4, mb);
            bulk_g2s(smem_u32(buf + G * N_ELEM),
                     e  + (size_t)ng * G * N_ELEM, G * N_ELEM * 4, mb);
        }

        // --- gather: one LDS.128 rec + one LDS.128 axial per edge, 4 batches ---
        float4 ax = make_float4(0.f, 0.f, 0.f, 0.f);
        float4 ay = make_float4(0.f, 0.f, 0.f, 0.f);
        for (int p = nbeg; p < nend; p++) {
            float4 rec = s_csr[p];
            float4 a   = s_axial[__float_as_int(rec.x)];
            ax.x += a.x * rec.y;  ax.y += a.y * rec.y;
            ax.z += a.z * rec.y;  ax.w += a.w * rec.y;
            ay.x += a.x * rec.z;  ay.y += a.y * rec.z;
            ay.z += a.z * rec.z;  ay.w += a.w * rec.z;
        }

        const float* axp = (const float*)&ax;
        const float* ayp = (const float*)&ay;
        #pragma unroll
        for (int g = 0; g < G; g++) {
            float dx = axp[g] - qq[g].x - rr[g].x;
            float dy = ayp[g] - qq[g].y - rr[g].y;
            acc += dx * dx + dy * dy;
        }
        __syncthreads();   // axial consumed before next build overwrites it
    }

    // --- block reduce ---
    #pragma unroll
    for (int o = 16; o > 0; o >>= 1)
        acc += __shfl_down_sync(0xffffffffu, acc, o);
    if ((tid & 31) == 0) s_warp[tid >> 5] = acc;
    __syncthreads();
    if (tid == 0) {
        float total = 0.f;
        #pragma unroll
        for (int w = 0; w < THREADS / 32; w++) total += s_warp[w];
        g_part[blockIdx.x] = total;
    }

    // --- last-block finalize (fixed-order double sum -> deterministic) ---
    __threadfence();
    if (tid == 0) {
        int old = atomicAdd(&g_ctr, 1);
        s_islast = (old == (int)gridDim.x - 1) ? 1 : 0;
    }
    __syncthreads();
    if (s_islast) {
        __threadfence();
        // overlay the (fully consumed) CSR region with the double scratch
        double* s_d = (double*)(dyn + OFF_CSR);
        double d = 0.0;
        #pragma unroll
        for (int i = tid; i < NBLK; i += THREADS) d += (double)g_part[i];
        s_d[tid] = d;
        __syncthreads();
        #pragma unroll
        for (int s = THREADS / 2; s > 0; s >>= 1) {
            if (tid < s) s_d[tid] += s_d[tid + s];
            __syncthreads();
        }
        if (tid == 0) {
            out[0] = (float)(s_d[0] / ((double)B * (double)N_NODES * 2.0));
            g_ctr = 0;   // reset for next graph replay
        }
    }
}

extern "C" void kernel_launch(void* const* d_in, const int* in_sizes, int n_in,
                              void* d_out, int out_size) {
    const float* EA       = (const float*)d_in[0];
    const float* e        = (const float*)d_in[1];
    const float* q        = (const float*)d_in[2];
    const float* r        = (const float*)d_in[3];
    const float* vecs     = (const float*)d_in[4];
    const int*   node_ids = (const int*)d_in[5];
    const int*   elem_ids = (const int*)d_in[6];
    float* out = (float*)d_out;

    static int configured = 0;
    if (!configured) {
        cudaFuncSetAttribute(nel_main_kernel,
                             cudaFuncAttributeMaxDynamicSharedMemorySize,
                             SMEM_BYTES);
        configured = 1;
    }

    nel_setup_kernel<<<1, N_NODES>>>(node_ids, elem_ids, vecs);
    nel_main_kernel<<<NBLK, THREADS, SMEM_BYTES>>>(EA, e, q, r, out);
}